// round 9
// baseline (speedup 1.0000x reference)
#include <cuda_runtime.h>

#define HEADS 8
#define FH 16
#define DIN 16
#define CH 128
#define NMAX 100000

// ---------------- scratch (device globals; no allocation allowed) -------------
__device__ __align__(16) float g_xp [NMAX * CH];   // per-node transformed features
__device__ __align__(16) float g_acc[NMAX * CH];   // sum_e ee * xp[src]
__device__ __align__(16) float g_als[NMAX * HEADS];
__device__ __align__(16) float g_ald[NMAX * HEADS];
__device__ __align__(16) float g_den[NMAX * HEADS];
__device__ __align__(16) float g_xgsum[CH];
__device__ __align__(16) float g_ga[CH];

// ---------------- block reductions (128 threads) ------------------------------
__device__ __forceinline__ float blockSum128(float v, float* sc) {
    v += __shfl_xor_sync(0xffffffffu, v, 16);
    v += __shfl_xor_sync(0xffffffffu, v, 8);
    v += __shfl_xor_sync(0xffffffffu, v, 4);
    v += __shfl_xor_sync(0xffffffffu, v, 2);
    v += __shfl_xor_sync(0xffffffffu, v, 1);
    __syncthreads();
    if ((threadIdx.x & 31) == 0) sc[threadIdx.x >> 5] = v;
    __syncthreads();
    return sc[0] + sc[1] + sc[2] + sc[3];
}
__device__ __forceinline__ float blockMax128(float v, float* sc) {
    v = fmaxf(v, __shfl_xor_sync(0xffffffffu, v, 16));
    v = fmaxf(v, __shfl_xor_sync(0xffffffffu, v, 8));
    v = fmaxf(v, __shfl_xor_sync(0xffffffffu, v, 4));
    v = fmaxf(v, __shfl_xor_sync(0xffffffffu, v, 2));
    v = fmaxf(v, __shfl_xor_sync(0xffffffffu, v, 1));
    __syncthreads();
    if ((threadIdx.x & 31) == 0) sc[threadIdx.x >> 5] = v;
    __syncthreads();
    return fmaxf(fmaxf(sc[0], sc[1]), fmaxf(sc[2], sc[3]));
}

// ---------------- kernel 1: node prep (xp, attention logits, self-loop init) --
__global__ void __launch_bounds__(128)
node_prep(const float* __restrict__ x, const float* __restrict__ Wc,
          const float* __restrict__ asrc, const float* __restrict__ adst,
          int N) {
    __shared__ float Wsh[HEADS * DIN * FH];       // 2048 floats
    __shared__ float as_sh[CH], ad_sh[CH];
    __shared__ float xsh[DIN];
    const int tid = threadIdx.x;                  // 128 threads
    for (int i = tid; i < HEADS * DIN * FH; i += 128) Wsh[i] = Wc[i];
    as_sh[tid] = asrc[tid];
    ad_sh[tid] = adst[tid];
    if (blockIdx.x == 0) g_xgsum[tid] = 0.f;      // consumed only in a later kernel
    __syncthreads();

    const int h = tid >> 4, f = tid & 15;
    for (int n = blockIdx.x; n < N; n += gridDim.x) {
        if (tid < DIN) xsh[tid] = x[n * DIN + tid];
        __syncthreads();
        float v = 0.f;
#pragma unroll
        for (int d = 0; d < DIN; d++) v = fmaf(xsh[d], Wsh[h * DIN * FH + d * FH + f], v);
        g_xp[n * CH + tid] = v;

        float ps = v * as_sh[tid];
        float pd = v * ad_sh[tid];
#pragma unroll
        for (int o = 8; o; o >>= 1) {             // reduce over the 16 f-lanes
            ps += __shfl_xor_sync(0xffffffffu, ps, o);
            pd += __shfl_xor_sync(0xffffffffu, pd, o);
        }
        // self-loop edge (n -> n): e = lrelu(al_src[n]+al_dst[n], 0.2)
        float e = ps + pd;
        e = e > 0.f ? e : 0.2f * e;
        float ee = __expf(e);
        if (f == 0) {
            g_als[n * HEADS + h] = ps;
            g_ald[n * HEADS + h] = pd;
            g_den[n * HEADS + h] = ee;            // init = self-loop contribution
        }
        g_acc[n * CH + tid] = ee * v;             // init accumulator with self-loop msg
        __syncthreads();
    }
}

// ---------------- kernel 2: edge pass (4 threads / edge) ----------------------
// edge_index is int32 on device (JAX int64 is coerced to int32 without x64;
// the R4 long-long read crashed, confirming the layout is 32-bit).
__global__ void __launch_bounds__(256)
edge_pass(const int* __restrict__ ei, int E) {
    long long gid = (long long)blockIdx.x * blockDim.x + threadIdx.x;
    int i = (int)(gid >> 2);
    int p = (int)(gid & 3);                       // covers heads 2p, 2p+1 (32 floats)
    if (i >= E) return;

    // only the quad leader loads the indices; broadcast to the other 3 lanes
    int sv = 0, dv = 0;
    if (p == 0) { sv = ei[i]; dv = ei[E + i]; }
    const unsigned base = (threadIdx.x & 31) & ~3u;
    const int s = __shfl_sync(0xffffffffu, sv, base);
    const int d = __shfl_sync(0xffffffffu, dv, base);

    // front-batch ALL independent loads (logits + 8x128b gather) -> max MLP
    const float2 a = *(const float2*)(g_als + (size_t)s * HEADS + p * 2);
    const float2 b = *(const float2*)(g_ald + (size_t)d * HEADS + p * 2);
    const float4* xs = (const float4*)(g_xp + (size_t)s * CH) + p * 8;
    float4 v0 = xs[0], v1 = xs[1], v2 = xs[2], v3 = xs[3];
    float4 v4 = xs[4], v5 = xs[5], v6 = xs[6], v7 = xs[7];

    float e0 = a.x + b.x; e0 = e0 > 0.f ? e0 : 0.2f * e0;
    float e1 = a.y + b.y; e1 = e1 > 0.f ? e1 : 0.2f * e1;
    const float ee0 = __expf(e0);
    const float ee1 = __expf(e1);
    atomicAdd((float2*)(g_den + (size_t)d * HEADS + p * 2), make_float2(ee0, ee1));

    float4* ac = (float4*)(g_acc + (size_t)d * CH) + p * 8;
#define SCALE_RED(j, vv, sc) \
    { vv.x *= sc; vv.y *= sc; vv.z *= sc; vv.w *= sc; atomicAdd(ac + j, vv); }
    SCALE_RED(0, v0, ee0) SCALE_RED(1, v1, ee0) SCALE_RED(2, v2, ee0) SCALE_RED(3, v3, ee0)
    SCALE_RED(4, v4, ee1) SCALE_RED(5, v5, ee1) SCALE_RED(6, v6, ee1) SCALE_RED(7, v7, ee1)
#undef SCALE_RED
}

// ---------------- kernel 3: per-node epilogue ---------------------------------
// x_local = acc/den + b ; att = softmax(lrelu(x@W^T+b,0.01)) ; x2 = lrelu(x*att,0.2)
// y = LN(x2@W^T+b) ; y /= ||y||2 ; accumulate column sums for global attention
__global__ void __launch_bounds__(128)
finalize(const float* __restrict__ fcW, const float* __restrict__ fcb,
         const float* __restrict__ bconv,
         const float* __restrict__ lng, const float* __restrict__ lnb,
         float* __restrict__ out, int N) {
    extern __shared__ float Wt[];                 // [128][129] transposed, padded
    __shared__ float xsh[CH], x2sh[CH], sc[4];
    const int tid = threadIdx.x;                  // 128 threads
    for (int i = tid; i < CH * CH; i += 128)
        Wt[(i & 127) * 129 + (i >> 7)] = fcW[i];  // Wt[k*129+c] = fcW[c][k]
    const float bc = bconv[tid];
    const float fb = fcb[tid];
    const float g  = lng[tid];
    const float be = lnb[tid];
    __syncthreads();

    float xg_part = 0.f;
    for (int n = blockIdx.x; n < N; n += gridDim.x) {
        const float den = g_den[n * HEADS + (tid >> 4)];
        const float xl  = g_acc[n * CH + tid] / den + bc;
        xsh[tid] = xl;
        __syncthreads();

        float z = fb;
#pragma unroll 16
        for (int k = 0; k < CH; k++) z = fmaf(xsh[k], Wt[k * 129 + tid], z);
        z = z > 0.f ? z : 0.01f * z;
        const float m  = blockMax128(z, sc);
        const float ez = __expf(z - m);
        const float ss = blockSum128(ez, sc);
        float x2 = xl * (ez / ss);
        x2 = x2 > 0.f ? x2 : 0.2f * x2;
        x2sh[tid] = x2;
        __syncthreads();

        float z2 = fb;
#pragma unroll 16
        for (int k = 0; k < CH; k++) z2 = fmaf(x2sh[k], Wt[k * 129 + tid], z2);

        const float mu  = blockSum128(z2, sc) * (1.f / 128.f);
        const float dz  = z2 - mu;
        const float var = blockSum128(dz * dz, sc) * (1.f / 128.f);
        float y = dz * rsqrtf(var + 1e-5f) * g + be;
        const float sq  = blockSum128(y * y, sc);
        y = y / fmaxf(sqrtf(sq), 1e-12f);

        out[(size_t)n * CH + tid] = y;
        xg_part += y;
        __syncthreads();
    }
    atomicAdd(&g_xgsum[tid], xg_part);
}

// ---------------- kernel 4: global attention (1 block) ------------------------
__global__ void __launch_bounds__(128)
global_att(const float* __restrict__ gW, const float* __restrict__ gb, float invN) {
    __shared__ float xg[CH], sc[4];
    const int tid = threadIdx.x;
    xg[tid] = g_xgsum[tid] * invN;
    __syncthreads();
    float z = gb[tid];
#pragma unroll 16
    for (int k = 0; k < CH; k++) z = fmaf(xg[k], gW[tid * CH + k], z);
    z = fmaxf(z, 0.f);
    const float m = blockMax128(z, sc);
    const float e = __expf(z - m);
    const float s = blockSum128(e, sc);
    g_ga[tid] = e / s;
}

// ---------------- kernel 5: scale output by global attention ------------------
__global__ void __launch_bounds__(256)
scale_out(float* __restrict__ out, int total4) {
    int i = blockIdx.x * blockDim.x + threadIdx.x;
    if (i >= total4) return;
    float4 v = ((float4*)out)[i];
    const float4 ga = ((const float4*)g_ga)[i & 31];
    v.x *= ga.x; v.y *= ga.y; v.z *= ga.z; v.w *= ga.w;
    ((float4*)out)[i] = v;
}

// ---------------- launch ------------------------------------------------------
extern "C" void kernel_launch(void* const* d_in, const int* in_sizes, int n_in,
                              void* d_out, int out_size) {
    const float* x     = (const float*)d_in[0];
    const int*   ei    = (const int*)d_in[1];      // int32 (JAX coerces int64)
    const float* Wc    = (const float*)d_in[2];
    const float* asrc  = (const float*)d_in[3];
    const float* adst  = (const float*)d_in[4];
    const float* bconv = (const float*)d_in[5];
    const float* fcW   = (const float*)d_in[6];
    const float* fcb   = (const float*)d_in[7];
    const float* lng   = (const float*)d_in[8];
    const float* lnb   = (const float*)d_in[9];
    const float* gW    = (const float*)d_in[10];
    const float* gb    = (const float*)d_in[11];
    float* out = (float*)d_out;

    const int N = in_sizes[0] / DIN;
    const int E = in_sizes[1] / 2;
    const int smem = CH * 129 * sizeof(float);    // 66048 B

    cudaFuncSetAttribute(finalize, cudaFuncAttributeMaxDynamicSharedMemorySize, smem);

    node_prep<<<1184, 128>>>(x, Wc, asrc, adst, N);
    {
        long long threads = 4LL * E;
        int blocks = (int)((threads + 255) / 256);
        edge_pass<<<blocks, 256>>>(ei, E);
    }
    finalize<<<444, 128, smem>>>(fcW, fcb, bconv, lng, lnb, out, N);
    global_att<<<1, 128>>>(gW, gb, 1.0f / (float)N);
    {
        int total4 = N * (CH / 4);
        scale_out<<<(total4 + 255) / 256, 256>>>(out, total4);
    }
}

// round 10
// speedup vs baseline: 1.1762x; 1.1762x over previous
#include <cuda_runtime.h>

#define HEADS 8
#define FH 16
#define DIN 16
#define CH 128
#define NMAX 100000
#define EMAX 1600000

// ---------------- scratch (device globals; no allocation allowed) -------------
__device__ __align__(16) float g_xp [NMAX * CH];   // per-node transformed features
__device__ __align__(16) float g_acc[NMAX * CH];   // self-loop + sum_e ee * xp[src]
__device__ __align__(16) float g_als[NMAX * HEADS];
__device__ __align__(16) float g_ald[NMAX * HEADS];
__device__ __align__(16) float g_den[NMAX * HEADS];
__device__ __align__(16) float g_xgsum[CH];
__device__ __align__(16) float g_ga[CH];
// CSR build scratch
__device__ int g_cnt[NMAX];
__device__ int g_off[NMAX];
__device__ int g_cur[NMAX];
__device__ int g_bsum[128];
__device__ int g_csr[EMAX + 32];

// ---------------- reductions for 256-thread blocks (warps 4-7 duplicate 0-3) --
__device__ __forceinline__ float blockSumHalf(float v, float* sc) {
    v += __shfl_xor_sync(0xffffffffu, v, 16);
    v += __shfl_xor_sync(0xffffffffu, v, 8);
    v += __shfl_xor_sync(0xffffffffu, v, 4);
    v += __shfl_xor_sync(0xffffffffu, v, 2);
    v += __shfl_xor_sync(0xffffffffu, v, 1);
    __syncthreads();
    if ((threadIdx.x & 31) == 0) sc[threadIdx.x >> 5] = v;
    __syncthreads();
    return sc[0] + sc[1] + sc[2] + sc[3];      // warps 4-7 are duplicates: exact
}
__device__ __forceinline__ float blockMaxHalf(float v, float* sc) {
    v = fmaxf(v, __shfl_xor_sync(0xffffffffu, v, 16));
    v = fmaxf(v, __shfl_xor_sync(0xffffffffu, v, 8));
    v = fmaxf(v, __shfl_xor_sync(0xffffffffu, v, 4));
    v = fmaxf(v, __shfl_xor_sync(0xffffffffu, v, 2));
    v = fmaxf(v, __shfl_xor_sync(0xffffffffu, v, 1));
    __syncthreads();
    if ((threadIdx.x & 31) == 0) sc[threadIdx.x >> 5] = v;
    __syncthreads();
    return fmaxf(fmaxf(sc[0], sc[1]), fmaxf(sc[2], sc[3]));
}
__device__ __forceinline__ float blockMax128(float v, float* sc) {
    v = fmaxf(v, __shfl_xor_sync(0xffffffffu, v, 16));
    v = fmaxf(v, __shfl_xor_sync(0xffffffffu, v, 8));
    v = fmaxf(v, __shfl_xor_sync(0xffffffffu, v, 4));
    v = fmaxf(v, __shfl_xor_sync(0xffffffffu, v, 2));
    v = fmaxf(v, __shfl_xor_sync(0xffffffffu, v, 1));
    __syncthreads();
    if ((threadIdx.x & 31) == 0) sc[threadIdx.x >> 5] = v;
    __syncthreads();
    return fmaxf(fmaxf(sc[0], sc[1]), fmaxf(sc[2], sc[3]));
}
__device__ __forceinline__ float blockSum128(float v, float* sc) {
    v += __shfl_xor_sync(0xffffffffu, v, 16);
    v += __shfl_xor_sync(0xffffffffu, v, 8);
    v += __shfl_xor_sync(0xffffffffu, v, 4);
    v += __shfl_xor_sync(0xffffffffu, v, 2);
    v += __shfl_xor_sync(0xffffffffu, v, 1);
    __syncthreads();
    if ((threadIdx.x & 31) == 0) sc[threadIdx.x >> 5] = v;
    __syncthreads();
    return sc[0] + sc[1] + sc[2] + sc[3];
}

// ---------------- kernel 1: node prep (xp, logits, self-loop init) ------------
__global__ void __launch_bounds__(128)
node_prep(const float* __restrict__ x, const float* __restrict__ Wc,
          const float* __restrict__ asrc, const float* __restrict__ adst,
          int N) {
    __shared__ float Wsh[HEADS * DIN * FH];
    __shared__ float as_sh[CH], ad_sh[CH];
    __shared__ float xsh[DIN];
    const int tid = threadIdx.x;
    for (int i = tid; i < HEADS * DIN * FH; i += 128) Wsh[i] = Wc[i];
    as_sh[tid] = asrc[tid];
    ad_sh[tid] = adst[tid];
    if (blockIdx.x == 0) g_xgsum[tid] = 0.f;
    __syncthreads();

    const int h = tid >> 4, f = tid & 15;
    for (int n = blockIdx.x; n < N; n += gridDim.x) {
        if (tid < DIN) xsh[tid] = x[n * DIN + tid];
        __syncthreads();
        float v = 0.f;
#pragma unroll
        for (int d = 0; d < DIN; d++) v = fmaf(xsh[d], Wsh[h * DIN * FH + d * FH + f], v);
        g_xp[n * CH + tid] = v;

        float ps = v * as_sh[tid];
        float pd = v * ad_sh[tid];
#pragma unroll
        for (int o = 8; o; o >>= 1) {
            ps += __shfl_xor_sync(0xffffffffu, ps, o);
            pd += __shfl_xor_sync(0xffffffffu, pd, o);
        }
        float e = ps + pd;                       // self-loop logit
        e = e > 0.f ? e : 0.2f * e;
        float ee = __expf(e);
        if (f == 0) {
            g_als[n * HEADS + h] = ps;
            g_ald[n * HEADS + h] = pd;
            g_den[n * HEADS + h] = ee;
        }
        g_acc[n * CH + tid] = ee * v;
        __syncthreads();
    }
}

// ---------------- CSR build ----------------------------------------------------
__global__ void __launch_bounds__(256) zero_cnt(int N) {
    int i = blockIdx.x * 256 + threadIdx.x;
    if (i < N) g_cnt[i] = 0;
}
__global__ void __launch_bounds__(256) hist(const int* __restrict__ ei, int E) {
    int i = blockIdx.x * 256 + threadIdx.x;
    if (i < E) atomicAdd(&g_cnt[ei[E + i]], 1);
}
__global__ void __launch_bounds__(1024) scan1(int N) {
    __shared__ int wsum[32];
    int i = blockIdx.x * 1024 + threadIdx.x;
    int v = (i < N) ? g_cnt[i] : 0;
    int lane = threadIdx.x & 31, wid = threadIdx.x >> 5;
    int inc = v;
#pragma unroll
    for (int o = 1; o < 32; o <<= 1) {
        int t = __shfl_up_sync(0xffffffffu, inc, o);
        if (lane >= o) inc += t;
    }
    if (lane == 31) wsum[wid] = inc;
    __syncthreads();
    if (wid == 0) {
        int wv = wsum[lane];
        int winc = wv;
#pragma unroll
        for (int o = 1; o < 32; o <<= 1) {
            int t = __shfl_up_sync(0xffffffffu, winc, o);
            if (lane >= o) winc += t;
        }
        wsum[lane] = winc - wv;                  // exclusive warp prefix
        if (lane == 31) g_bsum[blockIdx.x] = winc;  // block total
    }
    __syncthreads();
    if (i < N) g_off[i] = inc - v + wsum[wid];   // block-local exclusive scan
}
__global__ void __launch_bounds__(128) scan2(int nb) {
    __shared__ int ws[4];
    int t = threadIdx.x;
    int v = (t < nb) ? g_bsum[t] : 0;
    int lane = t & 31, wid = t >> 5;
    int inc = v;
#pragma unroll
    for (int o = 1; o < 32; o <<= 1) {
        int x = __shfl_up_sync(0xffffffffu, inc, o);
        if (lane >= o) inc += x;
    }
    if (lane == 31) ws[wid] = inc;
    __syncthreads();
    int wpre = 0;
    for (int wj = 0; wj < wid; wj++) wpre += ws[wj];
    if (t < nb) g_bsum[t] = inc - v + wpre;      // exclusive block prefix
}
__global__ void __launch_bounds__(1024) scan3(int N) {
    int i = blockIdx.x * 1024 + threadIdx.x;
    if (i < N) {
        g_off[i] += g_bsum[blockIdx.x];
        g_cur[i] = 0;
    }
}
__global__ void __launch_bounds__(256) scatter(const int* __restrict__ ei, int E) {
    int i = blockIdx.x * 256 + threadIdx.x;
    if (i >= E) return;
    int s = ei[i];
    int d = ei[E + i];
    int pos = g_off[d] + atomicAdd(&g_cur[d], 1);
    g_csr[pos] = s;
}

// ---------------- gather-reduce: one warp per dst node -------------------------
__global__ void __launch_bounds__(256)
gather(int N) {
    int warp = (blockIdx.x * 256 + threadIdx.x) >> 5;
    int l = threadIdx.x & 31;
    if (warp >= N) return;
    const int n = warp;
    const int h = l >> 2;                        // 4 lanes per head
    const float ald = g_ald[n * HEADS + h];
    const int beg = g_off[n];
    const int cnt = g_cnt[n];
    const float4* xp4 = (const float4*)g_xp;

    float4 acc = ((const float4*)(g_acc + (size_t)n * CH))[l];  // self-loop init
    float den = 0.f;

    for (int e = 0; e < cnt; e += 2) {
        const int s0 = g_csr[beg + e];
        const bool two = (e + 1 < cnt);
        const int s1 = two ? g_csr[beg + e + 1] : s0;
        // front-batch independent loads
        const float al0 = g_als[(size_t)s0 * HEADS + h];
        const float4 x0 = xp4[(size_t)s0 * 32 + l];
        float al1 = two ? g_als[(size_t)s1 * HEADS + h] : -1e30f;
        const float4 x1 = xp4[(size_t)s1 * 32 + l];

        float e0 = al0 + ald; e0 = e0 > 0.f ? e0 : 0.2f * e0;
        float e1 = al1 + ald; e1 = e1 > 0.f ? e1 : 0.2f * e1;
        const float ee0 = __expf(e0);
        const float ee1 = __expf(e1);            // 0 when absent (al1=-1e30)
        acc.x = fmaf(ee0, x0.x, acc.x); acc.y = fmaf(ee0, x0.y, acc.y);
        acc.z = fmaf(ee0, x0.z, acc.z); acc.w = fmaf(ee0, x0.w, acc.w);
        acc.x = fmaf(ee1, x1.x, acc.x); acc.y = fmaf(ee1, x1.y, acc.y);
        acc.z = fmaf(ee1, x1.z, acc.z); acc.w = fmaf(ee1, x1.w, acc.w);
        den += ee0 + ee1;
    }
    ((float4*)(g_acc + (size_t)n * CH))[l] = acc;
    if ((l & 3) == 0) g_den[n * HEADS + h] += den;   // exclusive per node
}

// ---------------- finalize: register-weight matvecs, 256 threads ---------------
// thread t: channel c = t&127, half h = t>>7 owns fcW[c][h*64 .. h*64+63] in regs
__global__ void __launch_bounds__(256)
finalize(const float* __restrict__ fcW, const float* __restrict__ fcb,
         const float* __restrict__ bconv,
         const float* __restrict__ lng, const float* __restrict__ lnb,
         float* __restrict__ out, int N) {
    __shared__ float xsh[CH], x2sh[CH], part[256], sc[8];
    const int tid = threadIdx.x;
    const int c = tid & 127, hf = tid >> 7;

    float4 w4[16];
    {
        const float4* wp = (const float4*)(fcW + (size_t)c * CH + hf * 64);
#pragma unroll
        for (int k = 0; k < 16; k++) w4[k] = wp[k];
    }
    const float bc = bconv[c];
    const float fb = fcb[c];
    const float g  = lng[c];
    const float be = lnb[c];

    float xg_part = 0.f;
    for (int n = blockIdx.x; n < N; n += gridDim.x) {
        if (tid < 128) {
            const float den = g_den[n * HEADS + (c >> 4)];
            xsh[c] = g_acc[(size_t)n * CH + c] / den + bc;
        }
        __syncthreads();
        const float xl = xsh[c];

        float zp = 0.f;
#pragma unroll
        for (int k = 0; k < 16; k++) {
            const float* xk = xsh + hf * 64 + k * 4;
            zp = fmaf(xk[0], w4[k].x, zp);
            zp = fmaf(xk[1], w4[k].y, zp);
            zp = fmaf(xk[2], w4[k].z, zp);
            zp = fmaf(xk[3], w4[k].w, zp);
        }
        part[tid] = zp;
        __syncthreads();
        float z = part[c] + part[c + 128] + fb;
        z = z > 0.f ? z : 0.01f * z;

        const float m  = blockMaxHalf(z, sc);
        const float ez = __expf(z - m);
        const float ss = blockSumHalf(ez, sc);
        float x2 = xl * (ez / ss);
        x2 = x2 > 0.f ? x2 : 0.2f * x2;
        if (tid < 128) x2sh[c] = x2;
        __syncthreads();

        float zp2 = 0.f;
#pragma unroll
        for (int k = 0; k < 16; k++) {
            const float* xk = x2sh + hf * 64 + k * 4;
            zp2 = fmaf(xk[0], w4[k].x, zp2);
            zp2 = fmaf(xk[1], w4[k].y, zp2);
            zp2 = fmaf(xk[2], w4[k].z, zp2);
            zp2 = fmaf(xk[3], w4[k].w, zp2);
        }
        part[tid] = zp2;
        __syncthreads();
        const float z2 = part[c] + part[c + 128] + fb;

        const float mu  = blockSumHalf(z2, sc) * (1.f / 128.f);
        const float dz  = z2 - mu;
        const float var = blockSumHalf(dz * dz, sc) * (1.f / 128.f);
        float y = dz * rsqrtf(var + 1e-5f) * g + be;
        const float sq  = blockSumHalf(y * y, sc);
        y = y / fmaxf(sqrtf(sq), 1e-12f);

        if (tid < 128) {
            out[(size_t)n * CH + c] = y;
            xg_part += y;
        }
        __syncthreads();
    }
    if (tid < 128) atomicAdd(&g_xgsum[c], xg_part);
}

// ---------------- global attention (1 block) -----------------------------------
__global__ void __launch_bounds__(128)
global_att(const float* __restrict__ gW, const float* __restrict__ gb, float invN) {
    __shared__ float xg[CH], sc[4];
    const int tid = threadIdx.x;
    xg[tid] = g_xgsum[tid] * invN;
    __syncthreads();
    float z = gb[tid];
#pragma unroll 16
    for (int k = 0; k < CH; k++) z = fmaf(xg[k], gW[tid * CH + k], z);
    z = fmaxf(z, 0.f);
    const float m = blockMax128(z, sc);
    const float e = __expf(z - m);
    const float s = blockSum128(e, sc);
    g_ga[tid] = e / s;
}

// ---------------- scale output by global attention -----------------------------
__global__ void __launch_bounds__(256)
scale_out(float* __restrict__ out, int total4) {
    int i = blockIdx.x * blockDim.x + threadIdx.x;
    if (i >= total4) return;
    float4 v = ((float4*)out)[i];
    const float4 ga = ((const float4*)g_ga)[i & 31];
    v.x *= ga.x; v.y *= ga.y; v.z *= ga.z; v.w *= ga.w;
    ((float4*)out)[i] = v;
}

// ---------------- launch --------------------------------------------------------
extern "C" void kernel_launch(void* const* d_in, const int* in_sizes, int n_in,
                              void* d_out, int out_size) {
    const float* x     = (const float*)d_in[0];
    const int*   ei    = (const int*)d_in[1];      // int32 (JAX coerces int64)
    const float* Wc    = (const float*)d_in[2];
    const float* asrc  = (const float*)d_in[3];
    const float* adst  = (const float*)d_in[4];
    const float* bconv = (const float*)d_in[5];
    const float* fcW   = (const float*)d_in[6];
    const float* fcb   = (const float*)d_in[7];
    const float* lng   = (const float*)d_in[8];
    const float* lnb   = (const float*)d_in[9];
    const float* gW    = (const float*)d_in[10];
    const float* gb    = (const float*)d_in[11];
    float* out = (float*)d_out;

    const int N = in_sizes[0] / DIN;
    const int E = in_sizes[1] / 2;
    const int nb1024 = (N + 1023) / 1024;

    node_prep<<<1184, 128>>>(x, Wc, asrc, adst, N);
    zero_cnt<<<(N + 255) / 256, 256>>>(N);
    hist<<<(E + 255) / 256, 256>>>(ei, E);
    scan1<<<nb1024, 1024>>>(N);
    scan2<<<1, 128>>>(nb1024);
    scan3<<<nb1024, 1024>>>(N);
    scatter<<<(E + 255) / 256, 256>>>(ei, E);
    gather<<<(N * 32 + 255) / 256, 256>>>(N);
    finalize<<<444, 256>>>(fcW, fcb, bconv, lng, lnb, out, N);
    global_att<<<1, 128>>>(gW, gb, 1.0f / (float)N);
    scale_out<<<(N * (CH / 4) + 255) / 256, 256>>>(out, N * (CH / 4));
}

// round 14
// speedup vs baseline: 1.4270x; 1.2132x over previous
#include <cuda_runtime.h>
#include <cstdint>

#define HEADS 8
#define FH 16
#define DIN 16
#define CH 128
#define NMAX 100000
#define EMAX 1600000

// ---------------- scratch (device globals; no allocation allowed) -------------
__device__ __align__(16) float g_xp [NMAX * CH];
__device__ __align__(16) float g_acc[NMAX * CH];
__device__ __align__(16) float g_als[NMAX * HEADS];
__device__ __align__(16) float g_ald[NMAX * HEADS];
__device__ __align__(16) float g_den[NMAX * HEADS];
__device__ __align__(16) float g_xgsum[CH];
__device__ __align__(16) float g_ga[CH];
__device__ int g_cnt[NMAX];
__device__ int g_off[NMAX];
__device__ int g_cur[NMAX];
__device__ int g_csr[EMAX + 32];

// ---------------- packed block reductions (256 thr, warps 4-7 dup 0-3) --------
__device__ __forceinline__ float2 redMax2(float2 v, float2* s) {
#pragma unroll
    for (int o = 16; o; o >>= 1) {
        v.x = fmaxf(v.x, __shfl_xor_sync(0xffffffffu, v.x, o));
        v.y = fmaxf(v.y, __shfl_xor_sync(0xffffffffu, v.y, o));
    }
    __syncthreads();
    if ((threadIdx.x & 31) == 0) s[threadIdx.x >> 5] = v;
    __syncthreads();
    float2 r;
    r.x = fmaxf(fmaxf(s[0].x, s[1].x), fmaxf(s[2].x, s[3].x));
    r.y = fmaxf(fmaxf(s[0].y, s[1].y), fmaxf(s[2].y, s[3].y));
    return r;
}
__device__ __forceinline__ float2 redSum2(float2 v, float2* s) {
#pragma unroll
    for (int o = 16; o; o >>= 1) {
        v.x += __shfl_xor_sync(0xffffffffu, v.x, o);
        v.y += __shfl_xor_sync(0xffffffffu, v.y, o);
    }
    __syncthreads();
    if ((threadIdx.x & 31) == 0) s[threadIdx.x >> 5] = v;
    __syncthreads();
    float2 r;
    r.x = s[0].x + s[1].x + s[2].x + s[3].x;
    r.y = s[0].y + s[1].y + s[2].y + s[3].y;
    return r;
}
__device__ __forceinline__ float4 redSum4(float4 v, float4* s) {
#pragma unroll
    for (int o = 16; o; o >>= 1) {
        v.x += __shfl_xor_sync(0xffffffffu, v.x, o);
        v.y += __shfl_xor_sync(0xffffffffu, v.y, o);
        v.z += __shfl_xor_sync(0xffffffffu, v.z, o);
        v.w += __shfl_xor_sync(0xffffffffu, v.w, o);
    }
    __syncthreads();
    if ((threadIdx.x & 31) == 0) s[threadIdx.x >> 5] = v;
    __syncthreads();
    float4 r;
    r.x = s[0].x + s[1].x + s[2].x + s[3].x;
    r.y = s[0].y + s[1].y + s[2].y + s[3].y;
    r.z = s[0].z + s[1].z + s[2].z + s[3].z;
    r.w = s[0].w + s[1].w + s[2].w + s[3].w;
    return r;
}
// 128-thread variants for global_att
__device__ __forceinline__ float blockMax128(float v, float* sc) {
#pragma unroll
    for (int o = 16; o; o >>= 1) v = fmaxf(v, __shfl_xor_sync(0xffffffffu, v, o));
    __syncthreads();
    if ((threadIdx.x & 31) == 0) sc[threadIdx.x >> 5] = v;
    __syncthreads();
    return fmaxf(fmaxf(sc[0], sc[1]), fmaxf(sc[2], sc[3]));
}
__device__ __forceinline__ float blockSum128(float v, float* sc) {
#pragma unroll
    for (int o = 16; o; o >>= 1) v += __shfl_xor_sync(0xffffffffu, v, o);
    __syncthreads();
    if ((threadIdx.x & 31) == 0) sc[threadIdx.x >> 5] = v;
    __syncthreads();
    return sc[0] + sc[1] + sc[2] + sc[3];
}

// ---------------- zero scratch (cnt, cur, xgsum, csr tail) ---------------------
__global__ void __launch_bounds__(256) zero_scratch(int N, int E) {
    int i = blockIdx.x * 256 + threadIdx.x;
    if (i < N) { g_cnt[i] = 0; g_cur[i] = 0; }
    if (i < CH) g_xgsum[i] = 0.f;
    if (i < 32) g_csr[E + i] = 0;
}

// ---------------- histogram of dst ---------------------------------------------
__global__ void __launch_bounds__(256) hist(const int* __restrict__ ei, int E) {
    int i = blockIdx.x * 256 + threadIdx.x;
    if (i < E) atomicAdd(&g_cnt[ei[E + i]], 1);
}

// ---------------- single-block full exclusive scan ------------------------------
__global__ void __launch_bounds__(1024) scan_all(int N) {
    __shared__ int wsum[32];
    __shared__ int stot;
    const int tid = threadIdx.x, lane = tid & 31, wid = tid >> 5;
    int carry = 0;
    const int nch = (N + 1023) >> 10;
    for (int ch = 0; ch < nch; ch++) {
        const int i = (ch << 10) + tid;
        int v = (i < N) ? g_cnt[i] : 0;
        int inc = v;
#pragma unroll
        for (int o = 1; o < 32; o <<= 1) {
            int t = __shfl_up_sync(0xffffffffu, inc, o);
            if (lane >= o) inc += t;
        }
        if (lane == 31) wsum[wid] = inc;
        __syncthreads();
        if (wid == 0) {
            int wv = wsum[lane], winc = wv;
#pragma unroll
            for (int o = 1; o < 32; o <<= 1) {
                int t = __shfl_up_sync(0xffffffffu, winc, o);
                if (lane >= o) winc += t;
            }
            wsum[lane] = winc - wv;
            if (lane == 31) stot = winc;
        }
        __syncthreads();
        if (i < N) g_off[i] = carry + wsum[wid] + inc - v;
        carry += stot;
        __syncthreads();
    }
}

// ---------------- scatter src indices into CSR ----------------------------------
__global__ void __launch_bounds__(256) scatter(const int* __restrict__ ei, int E) {
    int i = blockIdx.x * 256 + threadIdx.x;
    if (i >= E) return;
    int s = ei[i];
    int d = ei[E + i];
    int pos = g_off[d] + atomicAdd(&g_cur[d], 1);
    g_csr[pos] = s;
}

// ---------------- node prep (xp, logits, self-loop init) ------------------------
__global__ void __launch_bounds__(128)
node_prep(const float* __restrict__ x, const float* __restrict__ Wc,
          const float* __restrict__ asrc, const float* __restrict__ adst,
          int N) {
    __shared__ float Wsh[HEADS * DIN * FH];
    __shared__ float as_sh[CH], ad_sh[CH];
    __shared__ float xsh[DIN];
    const int tid = threadIdx.x;
    for (int i = tid; i < HEADS * DIN * FH; i += 128) Wsh[i] = Wc[i];
    as_sh[tid] = asrc[tid];
    ad_sh[tid] = adst[tid];
    __syncthreads();

    const int h = tid >> 4, f = tid & 15;
    for (int n = blockIdx.x; n < N; n += gridDim.x) {
        if (tid < DIN) xsh[tid] = x[n * DIN + tid];
        __syncthreads();
        float v = 0.f;
#pragma unroll
        for (int d = 0; d < DIN; d++) v = fmaf(xsh[d], Wsh[h * DIN * FH + d * FH + f], v);
        g_xp[n * CH + tid] = v;

        float ps = v * as_sh[tid];
        float pd = v * ad_sh[tid];
#pragma unroll
        for (int o = 8; o; o >>= 1) {
            ps += __shfl_xor_sync(0xffffffffu, ps, o);
            pd += __shfl_xor_sync(0xffffffffu, pd, o);
        }
        float e = ps + pd;
        e = e > 0.f ? e : 0.2f * e;
        float ee = __expf(e);
        if (f == 0) {
            g_als[n * HEADS + h] = ps;
            g_ald[n * HEADS + h] = pd;
            g_den[n * HEADS + h] = ee;
        }
        g_acc[n * CH + tid] = ee * v;
        __syncthreads();
    }
}

// ---------------- gather-reduce: one warp per dst node, 4-edge unroll -----------
__global__ void __launch_bounds__(256)
gather(int N) {
    int warp = (blockIdx.x * 256 + threadIdx.x) >> 5;
    int l = threadIdx.x & 31;
    if (warp >= N) return;
    const int n = warp;
    const int h = l >> 2;
    const float ald = g_ald[n * HEADS + h];
    const int beg = g_off[n];
    const int cnt = g_cnt[n];
    const float4* xp4 = (const float4*)g_xp;

    float4 acc = ((const float4*)(g_acc + (size_t)n * CH))[l];
    float den = 0.f;

    for (int e = 0; e < cnt; e += 4) {
        // padded reads stay within g_csr[0..E+31]; tail zeros are valid indices
        const int s0 = g_csr[beg + e + 0];
        const int s1 = g_csr[beg + e + 1];
        const int s2 = g_csr[beg + e + 2];
        const int s3 = g_csr[beg + e + 3];
        float al0 = g_als[(size_t)s0 * HEADS + h];
        float al1 = g_als[(size_t)s1 * HEADS + h];
        float al2 = g_als[(size_t)s2 * HEADS + h];
        float al3 = g_als[(size_t)s3 * HEADS + h];
        const float4 x0 = xp4[(size_t)s0 * 32 + l];
        const float4 x1 = xp4[(size_t)s1 * 32 + l];
        const float4 x2 = xp4[(size_t)s2 * 32 + l];
        const float4 x3 = xp4[(size_t)s3 * 32 + l];
        al1 = (e + 1 < cnt) ? al1 : -1e30f;
        al2 = (e + 2 < cnt) ? al2 : -1e30f;
        al3 = (e + 3 < cnt) ? al3 : -1e30f;
        float t0 = al0 + ald; t0 = t0 > 0.f ? t0 : 0.2f * t0;
        float t1 = al1 + ald; t1 = t1 > 0.f ? t1 : 0.2f * t1;
        float t2 = al2 + ald; t2 = t2 > 0.f ? t2 : 0.2f * t2;
        float t3 = al3 + ald; t3 = t3 > 0.f ? t3 : 0.2f * t3;
        const float ee0 = __expf(t0), ee1 = __expf(t1);
        const float ee2 = __expf(t2), ee3 = __expf(t3);
        acc.x = fmaf(ee0, x0.x, fmaf(ee1, x1.x, fmaf(ee2, x2.x, fmaf(ee3, x3.x, acc.x))));
        acc.y = fmaf(ee0, x0.y, fmaf(ee1, x1.y, fmaf(ee2, x2.y, fmaf(ee3, x3.y, acc.y))));
        acc.z = fmaf(ee0, x0.z, fmaf(ee1, x1.z, fmaf(ee2, x2.z, fmaf(ee3, x3.z, acc.z))));
        acc.w = fmaf(ee0, x0.w, fmaf(ee1, x1.w, fmaf(ee2, x2.w, fmaf(ee3, x3.w, acc.w))));
        den += (ee0 + ee1) + (ee2 + ee3);
    }
    ((float4*)(g_acc + (size_t)n * CH))[l] = acc;
    if ((l & 3) == 0) g_den[n * HEADS + h] += den;
}

// ---------------- finalize: FFMA2 matvecs, 2 nodes per iteration ----------------
__global__ void __launch_bounds__(256)
finalize(const float* __restrict__ fcW, const float* __restrict__ fcb,
         const float* __restrict__ bconv, const float* __restrict__ lng,
         const float* __restrict__ lnb, float* __restrict__ out, int N) {
    __shared__ __align__(16) float xsh[2][CH];
    __shared__ __align__(16) float x2sh[2][CH];
    __shared__ float part[2][256];
    __shared__ float4 sred[8];
    const int tid = threadIdx.x;
    const int c = tid & 127, hf = tid >> 7;

    uint64_t w2[32];
    {
        const uint64_t* wp = (const uint64_t*)(fcW + (size_t)c * CH + hf * 64);
#pragma unroll
        for (int k = 0; k < 32; k++) w2[k] = wp[k];
    }
    const float bc = bconv[c], fb = fcb[c], g = lng[c], be = lnb[c];

    float xg_part = 0.f;
    for (int base = blockIdx.x * 2; base < N; base += (gridDim.x << 1)) {
        const int n0 = base;
        const bool has1 = (base + 1 < N);
        const int nj = hf ? (has1 ? base + 1 : base) : base;
        {
            const float den = g_den[nj * HEADS + (c >> 4)];
            xsh[hf][c] = g_acc[(size_t)nj * CH + c] / den + bc;
        }
        __syncthreads();

        // matvec 1 (both nodes, f32x2-packed)
        {
            const uint64_t* xa = (const uint64_t*)(&xsh[0][hf * 64]);
            const uint64_t* xb = (const uint64_t*)(&xsh[1][hf * 64]);
            uint64_t aa = 0ull, ab = 0ull;
#pragma unroll
            for (int k = 0; k < 32; k++) {
                asm("fma.rn.f32x2 %0, %1, %2, %0;" : "+l"(aa) : "l"(xa[k]), "l"(w2[k]));
                asm("fma.rn.f32x2 %0, %1, %2, %0;" : "+l"(ab) : "l"(xb[k]), "l"(w2[k]));
            }
            float a0, a1, b0, b1;
            asm("mov.b64 {%0,%1},%2;" : "=f"(a0), "=f"(a1) : "l"(aa));
            asm("mov.b64 {%0,%1},%2;" : "=f"(b0), "=f"(b1) : "l"(ab));
            part[0][tid] = a0 + a1;
            part[1][tid] = b0 + b1;
        }
        __syncthreads();
        float za = part[0][c] + part[0][c + 128] + fb;
        float zb = part[1][c] + part[1][c + 128] + fb;
        za = za > 0.f ? za : 0.01f * za;
        zb = zb > 0.f ? zb : 0.01f * zb;

        const float2 m = redMax2(make_float2(za, zb), (float2*)sred);
        const float eza = __expf(za - m.x), ezb = __expf(zb - m.y);
        const float2 ss = redSum2(make_float2(eza, ezb), (float2*)sred);
        float x2a = xsh[0][c] * (eza / ss.x); x2a = x2a > 0.f ? x2a : 0.2f * x2a;
        float x2b = xsh[1][c] * (ezb / ss.y); x2b = x2b > 0.f ? x2b : 0.2f * x2b;
        if (hf == 0) x2sh[0][c] = x2a; else x2sh[1][c] = x2b;
        __syncthreads();

        // matvec 2
        {
            const uint64_t* xa = (const uint64_t*)(&x2sh[0][hf * 64]);
            const uint64_t* xb = (const uint64_t*)(&x2sh[1][hf * 64]);
            uint64_t aa = 0ull, ab = 0ull;
#pragma unroll
            for (int k = 0; k < 32; k++) {
                asm("fma.rn.f32x2 %0, %1, %2, %0;" : "+l"(aa) : "l"(xa[k]), "l"(w2[k]));
                asm("fma.rn.f32x2 %0, %1, %2, %0;" : "+l"(ab) : "l"(xb[k]), "l"(w2[k]));
            }
            float a0, a1, b0, b1;
            asm("mov.b64 {%0,%1},%2;" : "=f"(a0), "=f"(a1) : "l"(aa));
            asm("mov.b64 {%0,%1},%2;" : "=f"(b0), "=f"(b1) : "l"(ab));
            part[0][tid] = a0 + a1;
            part[1][tid] = b0 + b1;
        }
        __syncthreads();
        const float z2a = part[0][c] + part[0][c + 128] + fb;
        const float z2b = part[1][c] + part[1][c + 128] + fb;

        const float4 s4 = redSum4(make_float4(z2a, z2a * z2a, z2b, z2b * z2b), sred);
        const float mua = s4.x * (1.f / 128.f);
        const float vara = s4.y * (1.f / 128.f) - mua * mua;
        const float mub = s4.z * (1.f / 128.f);
        const float varb = s4.w * (1.f / 128.f) - mub * mub;
        float ya = (z2a - mua) * rsqrtf(vara + 1e-5f) * g + be;
        float yb = (z2b - mub) * rsqrtf(varb + 1e-5f) * g + be;
        const float2 sq = redSum2(make_float2(ya * ya, yb * yb), (float2*)sred);
        ya /= fmaxf(sqrtf(sq.x), 1e-12f);
        yb /= fmaxf(sqrtf(sq.y), 1e-12f);

        if (hf == 0) {
            out[(size_t)n0 * CH + c] = ya;
            xg_part += ya + (has1 ? yb : 0.f);
        } else if (has1) {
            out[(size_t)(base + 1) * CH + c] = yb;
        }
        __syncthreads();
    }
    if (hf == 0) atomicAdd(&g_xgsum[c], xg_part);
}

// ---------------- global attention (1 block) ------------------------------------
__global__ void __launch_bounds__(128)
global_att(const float* __restrict__ gW, const float* __restrict__ gb, float invN) {
    __shared__ float xg[CH], sc[4];
    const int tid = threadIdx.x;
    xg[tid] = g_xgsum[tid] * invN;
    __syncthreads();
    float z = gb[tid];
#pragma unroll 16
    for (int k = 0; k < CH; k++) z = fmaf(xg[k], gW[tid * CH + k], z);
    z = fmaxf(z, 0.f);
    const float m = blockMax128(z, sc);
    const float e = __expf(z - m);
    const float s = blockSum128(e, sc);
    g_ga[tid] = e / s;
}

// ---------------- scale output ---------------------------------------------------
__global__ void __launch_bounds__(256)
scale_out(float* __restrict__ out, int total4) {
    int i = blockIdx.x * blockDim.x + threadIdx.x;
    if (i >= total4) return;
    float4 v = ((float4*)out)[i];
    const float4 ga = ((const float4*)g_ga)[i & 31];
    v.x *= ga.x; v.y *= ga.y; v.z *= ga.z; v.w *= ga.w;
    ((float4*)out)[i] = v;
}

// ---------------- launch ----------------------------------------------------------
extern "C" void kernel_launch(void* const* d_in, const int* in_sizes, int n_in,
                              void* d_out, int out_size) {
    const float* x     = (const float*)d_in[0];
    const int*   ei    = (const int*)d_in[1];      // int32 (JAX coerces int64)
    const float* Wc    = (const float*)d_in[2];
    const float* asrc  = (const float*)d_in[3];
    const float* adst  = (const float*)d_in[4];
    const float* bconv = (const float*)d_in[5];
    const float* fcW   = (const float*)d_in[6];
    const float* fcb   = (const float*)d_in[7];
    const float* lng   = (const float*)d_in[8];
    const float* lnb   = (const float*)d_in[9];
    const float* gW    = (const float*)d_in[10];
    const float* gb    = (const float*)d_in[11];
    float* out = (float*)d_out;

    const int N = in_sizes[0] / DIN;
    const int E = in_sizes[1] / 2;

    zero_scratch<<<(N + 255) / 256, 256>>>(N, E);
    hist<<<(E + 255) / 256, 256>>>(ei, E);
    scan_all<<<1, 1024>>>(N);
    scatter<<<(E + 255) / 256, 256>>>(ei, E);
    node_prep<<<1184, 128>>>(x, Wc, asrc, adst, N);
    gather<<<(N * 32 + 255) / 256, 256>>>(N);
    finalize<<<444, 256>>>(fcW, fcb, bconv, lng, lnb, out, N);
    global_att<<<1, 128>>>(gW, gb, 1.0f / (float)N);
    scale_out<<<(N * (CH / 4) + 255) / 256, 256>>>(out, N * (CH / 4));
}